// round 6
// baseline (speedup 1.0000x reference)
#include <cuda_runtime.h>
#include <cuda_bf16.h>
#include <math.h>

// ---------------- problem constants (match dataset) ----------------
#define NMAXN 100000
#define EMAXE 1600000
#define HID 128
#define NOUT 10
#define BN_EPS 1e-5f

// ---------------- static device scratch (alloc-free rule) ----------------
__device__ __align__(256) float g_bufB[(size_t)NMAXN * HID]; // gemm output
__device__ __align__(256) float g_bufC[(size_t)NMAXN * HID]; // aggregation output
__device__ __align__(256) int   g_cnt[NMAXN];
__device__ __align__(256) int   g_rowstart[NMAXN + 1];
__device__ __align__(256) int   g_cursor[NMAXN];
__device__ __align__(256) int   g_src_sorted[EMAXE];
__device__ __align__(256) float g_dinv[NMAXN];
__device__ __align__(256) float g_cs[2][HID];   // per-layer column sums
__device__ __align__(256) float g_cq[2][HID];   // per-layer column sumsq
__device__ __align__(256) float g_scale[HID];
__device__ __align__(256) float g_shift[HID];
__device__ __align__(256) int   g_partials[256];
__device__ __align__(256) int   g_partials_scan[256];
__device__ int g_is64;   // 1 if edge_index is int64, 0 if int32

// ---------------- dtype detection ----------------
__global__ void k_detect(const unsigned int* __restrict__ raw) {
    __shared__ int any;
    if (threadIdx.x == 0) any = 0;
    __syncthreads();
    unsigned int w = raw[threadIdx.x * 2 + 1];
    if (w != 0u) atomicOr(&any, 1);
    __syncthreads();
    if (threadIdx.x == 0) g_is64 = any ? 0 : 1;
}

__device__ __forceinline__ int edge_at(const void* ei, size_t idx) {
    if (g_is64) return (int)((const long long*)ei)[idx];
    return ((const int*)ei)[idx];
}

// ---------------- CSR build ----------------
__global__ void k_zero(int n) {
    int i = blockIdx.x * blockDim.x + threadIdx.x;
    if (i < n) { g_cnt[i] = 0; g_cursor[i] = 0; }
    if (i < HID) {
        g_cs[0][i] = 0.f; g_cq[0][i] = 0.f;
        g_cs[1][i] = 0.f; g_cq[1][i] = 0.f;
    }
}

__global__ void k_count(const void* __restrict__ ei, int e, int n) {
    int i = blockIdx.x * blockDim.x + threadIdx.x;
    if (i < e) {
        int d = edge_at(ei, (size_t)e + i);
        if ((unsigned)d < (unsigned)n) atomicAdd(&g_cnt[d], 1);
    }
}

#define SCAN_B 1024
__global__ void k_scan1(int n) {
    __shared__ int sh[SCAN_B];
    int i = blockIdx.x * SCAN_B + threadIdx.x;
    int v = (i < n) ? g_cnt[i] : 0;
    sh[threadIdx.x] = v;
    __syncthreads();
    for (int off = 1; off < SCAN_B; off <<= 1) {
        int t = 0;
        if ((int)threadIdx.x >= off) t = sh[threadIdx.x - off];
        __syncthreads();
        if ((int)threadIdx.x >= off) sh[threadIdx.x] += t;
        __syncthreads();
    }
    if (i < n) g_rowstart[i] = sh[threadIdx.x];
    if (threadIdx.x == SCAN_B - 1) g_partials[blockIdx.x] = sh[SCAN_B - 1];
}

__global__ void k_scan2(int nb) {
    __shared__ int sh[256];
    int v = ((int)threadIdx.x < nb) ? g_partials[threadIdx.x] : 0;
    sh[threadIdx.x] = v;
    __syncthreads();
    for (int off = 1; off < 256; off <<= 1) {
        int t = 0;
        if ((int)threadIdx.x >= off) t = sh[threadIdx.x - off];
        __syncthreads();
        if ((int)threadIdx.x >= off) sh[threadIdx.x] += t;
        __syncthreads();
    }
    g_partials_scan[threadIdx.x] = sh[threadIdx.x] - v;
}

__global__ void k_scan3(int n) {
    int i = blockIdx.x * blockDim.x + threadIdx.x;
    if (i < n) {
        int cnt  = g_cnt[i];
        int incl = g_rowstart[i] + g_partials_scan[i / SCAN_B];
        g_rowstart[i] = incl - cnt;
        if (i == n - 1) g_rowstart[n] = incl;
        g_dinv[i] = rsqrtf((float)cnt + 1.0f);
    }
}

__global__ void k_bucket(const void* __restrict__ ei, int e, int n) {
    int i = blockIdx.x * blockDim.x + threadIdx.x;
    if (i < e) {
        int s = edge_at(ei, i);
        int d = edge_at(ei, (size_t)e + i);
        if ((unsigned)d < (unsigned)n && (unsigned)s < (unsigned)n) {
            int pos = atomicAdd(&g_cursor[d], 1);
            g_src_sorted[g_rowstart[d] + pos] = s;
        }
    }
}

// ---------------- Tensor-core GEMM: [n,128] @ [128,128] -> g_bufB ----------------
// bf16 split (hi/lo), 3 mma products ~= fp32 accuracy. mma.m16n8k16.
// Block: 64 rows x 128 cols, 256 threads = 8 warps (4 m x 2 n), warp tile 16x64.
// mode==0: A = Aext.  mode==1: A = relu(g_bufC * g_scale + g_shift).
#define GMB 64
#define GKB 32
#define GPAD 8
#define GSTR (GKB + GPAD)    // 40 bf16 = 80B = 20 words -> conflict-free frags

__device__ __forceinline__ void bf16_split(float v, __nv_bfloat16& hi, __nv_bfloat16& lo) {
    hi = __float2bfloat16_rn(v);
    lo = __float2bfloat16_rn(v - __bfloat162float(hi));
}

__device__ __forceinline__ void mma_bf16(
    float& c0, float& c1, float& c2, float& c3,
    unsigned a0, unsigned a1, unsigned a2, unsigned a3,
    unsigned b0, unsigned b1)
{
    asm volatile(
        "mma.sync.aligned.m16n8k16.row.col.f32.bf16.bf16.f32 "
        "{%0,%1,%2,%3}, {%4,%5,%6,%7}, {%8,%9}, {%0,%1,%2,%3};"
        : "+f"(c0), "+f"(c1), "+f"(c2), "+f"(c3)
        : "r"(a0), "r"(a1), "r"(a2), "r"(a3), "r"(b0), "r"(b1));
}

__global__ __launch_bounds__(256) void k_gemm_tc(
    const float* __restrict__ Aext, int mode,
    const float* __restrict__ W, int n)
{
    __shared__ __align__(16) __nv_bfloat16 Ah[GMB][GSTR];
    __shared__ __align__(16) __nv_bfloat16 Al[GMB][GSTR];
    __shared__ __align__(16) __nv_bfloat16 Wh[HID][GSTR];  // n-major: Wh[n][k]
    __shared__ __align__(16) __nv_bfloat16 Wl[HID][GSTR];

    int tid  = threadIdx.x;
    int warp = tid >> 5;
    int lane = tid & 31;
    int group = lane >> 2;      // 0..7
    int tig   = lane & 3;       // 0..3
    int wm = (warp >> 1) * 16;  // warp row offset 0/16/32/48
    int wn = (warp & 1) * 64;   // warp col offset 0/64
    int br = blockIdx.x * GMB;
    const float* A = mode ? (const float*)g_bufC : Aext;

    float acc[8][4];
#pragma unroll
    for (int j = 0; j < 8; j++)
#pragma unroll
        for (int q = 0; q < 4; q++) acc[j][q] = 0.f;

    for (int kb = 0; kb < HID; kb += GKB) {
        // ---- load + split A chunk: 64 rows x 32 k ----
#pragma unroll
        for (int u = 0; u < 2; u++) {
            int idx = tid + u * 256;        // 0..511 float4 slots
            int row = idx >> 3;             // 0..63
            int c4  = idx & 7;              // 0..7 (float4 within 32-k slab)
            int gr  = br + row;
            float4 v = make_float4(0.f, 0.f, 0.f, 0.f);
            if (gr < n) v = ((const float4*)A)[(size_t)gr * 32 + (kb >> 2) + c4];
            if (mode) {
                float4 sc = ((const float4*)g_scale)[(kb >> 2) + c4];
                float4 sh = ((const float4*)g_shift)[(kb >> 2) + c4];
                v.x = fmaxf(fmaf(v.x, sc.x, sh.x), 0.f);
                v.y = fmaxf(fmaf(v.y, sc.y, sh.y), 0.f);
                v.z = fmaxf(fmaf(v.z, sc.z, sh.z), 0.f);
                v.w = fmaxf(fmaf(v.w, sc.w, sh.w), 0.f);
            }
            int kc = c4 * 4;
            __nv_bfloat16 h, l;
            bf16_split(v.x, h, l); Ah[row][kc + 0] = h; Al[row][kc + 0] = l;
            bf16_split(v.y, h, l); Ah[row][kc + 1] = h; Al[row][kc + 1] = l;
            bf16_split(v.z, h, l); Ah[row][kc + 2] = h; Al[row][kc + 2] = l;
            bf16_split(v.w, h, l); Ah[row][kc + 3] = h; Al[row][kc + 3] = l;
        }
        // ---- load + split + transpose W chunk: 32 k x 128 n -> Ws[n][k] ----
#pragma unroll
        for (int u = 0; u < 4; u++) {
            int idx = tid + u * 256;        // 0..1023 float4 slots
            int r  = idx >> 5;              // k within chunk 0..31
            int c4 = idx & 31;              // 0..31 float4 along n
            float4 v = ((const float4*)W)[(size_t)(kb + r) * 32 + c4];
            int nb = c4 * 4;
            __nv_bfloat16 h, l;
            bf16_split(v.x, h, l); Wh[nb + 0][r] = h; Wl[nb + 0][r] = l;
            bf16_split(v.y, h, l); Wh[nb + 1][r] = h; Wl[nb + 1][r] = l;
            bf16_split(v.z, h, l); Wh[nb + 2][r] = h; Wl[nb + 2][r] = l;
            bf16_split(v.w, h, l); Wh[nb + 3][r] = h; Wl[nb + 3][r] = l;
        }
        __syncthreads();

#pragma unroll
        for (int ks = 0; ks < 2; ks++) {
            int k0 = ks * 16;
            // A fragments (16x16), hi and lo
            int ar0 = wm + group, ar1 = wm + group + 8;
            int ac0 = k0 + tig * 2, ac1 = k0 + tig * 2 + 8;
            unsigned ah0 = *(const unsigned*)&Ah[ar0][ac0];
            unsigned ah1 = *(const unsigned*)&Ah[ar1][ac0];
            unsigned ah2 = *(const unsigned*)&Ah[ar0][ac1];
            unsigned ah3 = *(const unsigned*)&Ah[ar1][ac1];
            unsigned al0 = *(const unsigned*)&Al[ar0][ac0];
            unsigned al1 = *(const unsigned*)&Al[ar1][ac0];
            unsigned al2 = *(const unsigned*)&Al[ar0][ac1];
            unsigned al3 = *(const unsigned*)&Al[ar1][ac1];
#pragma unroll
            for (int j = 0; j < 8; j++) {
                int nr = wn + j * 8 + group;
                unsigned bh0 = *(const unsigned*)&Wh[nr][ac0];
                unsigned bh1 = *(const unsigned*)&Wh[nr][ac1];
                unsigned bl0 = *(const unsigned*)&Wl[nr][ac0];
                unsigned bl1 = *(const unsigned*)&Wl[nr][ac1];
                mma_bf16(acc[j][0], acc[j][1], acc[j][2], acc[j][3],
                         ah0, ah1, ah2, ah3, bh0, bh1);
                mma_bf16(acc[j][0], acc[j][1], acc[j][2], acc[j][3],
                         ah0, ah1, ah2, ah3, bl0, bl1);
                mma_bf16(acc[j][0], acc[j][1], acc[j][2], acc[j][3],
                         al0, al1, al2, al3, bh0, bh1);
            }
        }
        __syncthreads();
    }
    // ---- store C fragments ----
    int row0 = br + wm + group;
    int row1 = row0 + 8;
#pragma unroll
    for (int j = 0; j < 8; j++) {
        int col = wn + j * 8 + tig * 2;
        if (row0 < n) *(float2*)&g_bufB[(size_t)row0 * HID + col]
            = make_float2(acc[j][0], acc[j][1]);
        if (row1 < n) *(float2*)&g_bufB[(size_t)row1 * HID + col]
            = make_float2(acc[j][2], acc[j][3]);
    }
}

// ---------------- small GEMM: relu(bn(g_bufC)) @ W2[128,10] -> g_bufB[n,10] ----------------
__global__ __launch_bounds__(256) void k_gemm10(
    const float* __restrict__ W, int n)
{
    __shared__ float Ws[HID * NOUT];
    int tid = threadIdx.x;
    for (int i = tid; i < HID * NOUT; i += blockDim.x) Ws[i] = W[i];
    __syncthreads();
    int warp = tid >> 5, lane = tid & 31;
    int row = blockIdx.x * (blockDim.x >> 5) + warp;
    if (row >= n) return;
    const float* A = (const float*)g_bufC;
    float a0 = fmaxf(fmaf(A[(size_t)row * HID + lane],      g_scale[lane],      g_shift[lane]),      0.f);
    float a1 = fmaxf(fmaf(A[(size_t)row * HID + 32 + lane], g_scale[lane + 32], g_shift[lane + 32]), 0.f);
    float a2 = fmaxf(fmaf(A[(size_t)row * HID + 64 + lane], g_scale[lane + 64], g_shift[lane + 64]), 0.f);
    float a3 = fmaxf(fmaf(A[(size_t)row * HID + 96 + lane], g_scale[lane + 96], g_shift[lane + 96]), 0.f);
#pragma unroll
    for (int c = 0; c < NOUT; c++) {
        float p = a0 * Ws[lane * NOUT + c]
                + a1 * Ws[(lane + 32) * NOUT + c]
                + a2 * Ws[(lane + 64) * NOUT + c]
                + a3 * Ws[(lane + 96) * NOUT + c];
#pragma unroll
        for (int off = 16; off > 0; off >>= 1)
            p += __shfl_down_sync(0xffffffffu, p, off);
        if (lane == 0) g_bufB[(size_t)row * NOUT + c] = p;
    }
}

// ---------------- aggregation + fused BN stats, width 128 ----------------
__global__ __launch_bounds__(256) void k_agg128(
    const float* __restrict__ bias, int n, int layer)
{
    __shared__ float shs[8][HID];
    __shared__ float shq[8][HID];
    int ty = threadIdx.y;
    int lane = threadIdx.x;
    int node = blockIdx.x * 8 + ty;
    bool active = node < n;
    const float4* hp = (const float4*)g_bufB;

    float4 o = make_float4(0.f, 0.f, 0.f, 0.f);
    if (active) {
        float di = g_dinv[node];
        float4 v = hp[(size_t)node * 32 + lane];
        float4 acc;
        acc.x = di * v.x; acc.y = di * v.y; acc.z = di * v.z; acc.w = di * v.w;
        int beg = g_rowstart[node], end = g_rowstart[node + 1];
        int j = beg;
        for (; j + 1 < end; j += 2) {
            int s0 = g_src_sorted[j];
            int s1 = g_src_sorted[j + 1];
            float w0 = g_dinv[s0];
            float w1 = g_dinv[s1];
            float4 m0 = hp[(size_t)s0 * 32 + lane];
            float4 m1 = hp[(size_t)s1 * 32 + lane];
            acc.x += w0 * m0.x + w1 * m1.x;
            acc.y += w0 * m0.y + w1 * m1.y;
            acc.z += w0 * m0.z + w1 * m1.z;
            acc.w += w0 * m0.w + w1 * m1.w;
        }
        if (j < end) {
            int s = g_src_sorted[j];
            float w = g_dinv[s];
            float4 m = hp[(size_t)s * 32 + lane];
            acc.x += w * m.x; acc.y += w * m.y; acc.z += w * m.z; acc.w += w * m.w;
        }
        float4 bb = ((const float4*)bias)[lane];
        o.x = fmaf(di, acc.x, bb.x); o.y = fmaf(di, acc.y, bb.y);
        o.z = fmaf(di, acc.z, bb.z); o.w = fmaf(di, acc.w, bb.w);
        ((float4*)g_bufC)[(size_t)node * 32 + lane] = o;
    }

    *(float4*)&shs[ty][lane * 4] = o;
    *(float4*)&shq[ty][lane * 4] = make_float4(o.x * o.x, o.y * o.y, o.z * o.z, o.w * o.w);
    __syncthreads();
    int tid = ty * 32 + lane;
    if (tid < HID) {
        float s = 0.f, q = 0.f;
#pragma unroll
        for (int r = 0; r < 8; r++) { s += shs[r][tid]; q += shq[r][tid]; }
        atomicAdd(&g_cs[layer][tid], s);
        atomicAdd(&g_cq[layer][tid], q);
    }
}

// width-10 variant (final layer): reads g_bufB[n,10], writes d_out
__global__ __launch_bounds__(256) void k_agg10(
    const float* __restrict__ bias, float* __restrict__ out, int n)
{
    int node = blockIdx.x * blockDim.y + threadIdx.y;
    if (node >= n) return;
    int lane = threadIdx.x;
    const float* h = (const float*)g_bufB;
    float di = g_dinv[node];
    float acc = 0.0f;
    if (lane < NOUT) acc = di * h[(size_t)node * NOUT + lane];
    int beg = g_rowstart[node], end = g_rowstart[node + 1];
    for (int j = beg; j < end; j++) {
        int s = g_src_sorted[j];
        if ((unsigned)s >= (unsigned)n) continue;
        float w = g_dinv[s];
        if (lane < NOUT) acc += w * h[(size_t)s * NOUT + lane];
    }
    if (lane < NOUT) out[(size_t)node * NOUT + lane] = di * acc + bias[lane];
}

// ---------------- BN finalize ----------------
__global__ __launch_bounds__(128) void k_bnfinal(
    const float* __restrict__ g, const float* __restrict__ be,
    int layer, int n)
{
    int c = threadIdx.x;
    float inv_n = 1.0f / (float)n;
    float mu  = g_cs[layer][c] * inv_n;
    float var = fmaxf(g_cq[layer][c] * inv_n - mu * mu, 0.0f);
    float sc = g[c] * rsqrtf(var + BN_EPS);
    g_scale[c] = sc;
    g_shift[c] = fmaf(-mu, sc, be[c]);
}

// ---------------- host launcher: kernel launches ONLY ----------------
extern "C" void kernel_launch(void* const* d_in, const int* in_sizes, int n_in,
                              void* d_out, int out_size)
{
    const float* x  = (const float*)d_in[0];
    const void*  ei = d_in[1];
    const float* W0 = (const float*)d_in[2];  const float* b0 = (const float*)d_in[3];
    const float* g0 = (const float*)d_in[4];  const float* be0 = (const float*)d_in[5];
    const float* W1 = (const float*)d_in[6];  const float* b1 = (const float*)d_in[7];
    const float* g1 = (const float*)d_in[8];  const float* be1 = (const float*)d_in[9];
    const float* W2 = (const float*)d_in[10]; const float* b2 = (const float*)d_in[11];

    int n = in_sizes[0] / HID;
    int e = in_sizes[1] / 2;
    float* out = (float*)d_out;

    int nb_n256 = (n + 255) / 256;
    int nb_e256 = (e + 255) / 256;
    int nb_scan = (n + SCAN_B - 1) / SCAN_B;

    // ---- dtype probe + CSR build ----
    k_detect<<<1, 256>>>((const unsigned int*)ei);
    k_zero<<<nb_n256, 256>>>(n);
    k_count<<<nb_e256, 256>>>(ei, e, n);
    k_scan1<<<nb_scan, SCAN_B>>>(n);
    k_scan2<<<1, 256>>>(nb_scan);
    k_scan3<<<nb_n256, 256>>>(n);
    k_bucket<<<nb_e256, 256>>>(ei, e, n);

    dim3 aggBlk(32, 8);
    int aggGrid = (n + 7) / 8;
    int gemmGrid = (n + GMB - 1) / GMB;

    // ---- layer 0 ----
    k_gemm_tc<<<gemmGrid, 256>>>(x, 0, W0, n);
    k_agg128<<<aggGrid, aggBlk>>>(b0, n, 0);
    k_bnfinal<<<1, 128>>>(g0, be0, 0, n);

    // ---- layer 1 (BN0 apply fused into A-load) ----
    k_gemm_tc<<<gemmGrid, 256>>>(x, 1, W1, n);
    k_agg128<<<aggGrid, aggBlk>>>(b1, n, 1);
    k_bnfinal<<<1, 128>>>(g1, be1, 1, n);

    // ---- layer 2 (BN1 apply fused into A-load; output) ----
    k_gemm10<<<(n + 7) / 8, 256>>>(W2, n);
    k_agg10<<<aggGrid, aggBlk>>>(b2, out, n);
}

// round 7
// speedup vs baseline: 1.3996x; 1.3996x over previous
#include <cuda_runtime.h>
#include <cuda_bf16.h>
#include <math.h>

// ---------------- problem constants (match dataset) ----------------
#define NMAXN 100000
#define EMAXE 1600000
#define HID 128
#define NOUT 10
#define BN_EPS 1e-5f

// ---------------- static device scratch (alloc-free rule) ----------------
__device__ __align__(256) float g_bufB[(size_t)NMAXN * HID]; // gemm output
__device__ __align__(256) float g_bufC[(size_t)NMAXN * HID]; // aggregation output
__device__ __align__(256) int   g_cnt[NMAXN];
__device__ __align__(256) int   g_rowstart[NMAXN + 1];
__device__ __align__(256) int   g_cursor[NMAXN];
__device__ __align__(256) int   g_src_sorted[EMAXE];
__device__ __align__(256) float g_dinv[NMAXN];
__device__ __align__(256) float g_cs[2][HID];   // per-layer column sums
__device__ __align__(256) float g_cq[2][HID];   // per-layer column sumsq
__device__ __align__(256) float g_scale[HID];
__device__ __align__(256) float g_shift[HID];
__device__ __align__(256) int   g_partials[256];
__device__ __align__(256) int   g_partials_scan[256];
// pre-split W (hi/lo bf16), transposed to [n][k] (n-major) for direct smem copy
__device__ __align__(256) __nv_bfloat16 g_Wh[HID * HID];
__device__ __align__(256) __nv_bfloat16 g_Wl[HID * HID];
__device__ int g_is64;   // 1 if edge_index is int64, 0 if int32

// ---------------- dtype detection ----------------
__global__ void k_detect(const unsigned int* __restrict__ raw) {
    __shared__ int any;
    if (threadIdx.x == 0) any = 0;
    __syncthreads();
    unsigned int w = raw[threadIdx.x * 2 + 1];
    if (w != 0u) atomicOr(&any, 1);
    __syncthreads();
    if (threadIdx.x == 0) g_is64 = any ? 0 : 1;
}

__device__ __forceinline__ int edge_at(const void* ei, size_t idx) {
    if (g_is64) return (int)((const long long*)ei)[idx];
    return ((const int*)ei)[idx];
}

// ---------------- CSR build ----------------
__global__ void k_zero(int n) {
    int i = blockIdx.x * blockDim.x + threadIdx.x;
    if (i < n) { g_cnt[i] = 0; g_cursor[i] = 0; }
    if (i < HID) {
        g_cs[0][i] = 0.f; g_cq[0][i] = 0.f;
        g_cs[1][i] = 0.f; g_cq[1][i] = 0.f;
    }
}

__global__ void k_count(const void* __restrict__ ei, int e, int n) {
    int i = blockIdx.x * blockDim.x + threadIdx.x;
    if (i < e) {
        int d = edge_at(ei, (size_t)e + i);
        if ((unsigned)d < (unsigned)n) atomicAdd(&g_cnt[d], 1);
    }
}

#define SCAN_B 1024
__global__ void k_scan1(int n) {
    __shared__ int sh[SCAN_B];
    int i = blockIdx.x * SCAN_B + threadIdx.x;
    int v = (i < n) ? g_cnt[i] : 0;
    sh[threadIdx.x] = v;
    __syncthreads();
    for (int off = 1; off < SCAN_B; off <<= 1) {
        int t = 0;
        if ((int)threadIdx.x >= off) t = sh[threadIdx.x - off];
        __syncthreads();
        if ((int)threadIdx.x >= off) sh[threadIdx.x] += t;
        __syncthreads();
    }
    if (i < n) g_rowstart[i] = sh[threadIdx.x];
    if (threadIdx.x == SCAN_B - 1) g_partials[blockIdx.x] = sh[SCAN_B - 1];
}

__global__ void k_scan2(int nb) {
    __shared__ int sh[256];
    int v = ((int)threadIdx.x < nb) ? g_partials[threadIdx.x] : 0;
    sh[threadIdx.x] = v;
    __syncthreads();
    for (int off = 1; off < 256; off <<= 1) {
        int t = 0;
        if ((int)threadIdx.x >= off) t = sh[threadIdx.x - off];
        __syncthreads();
        if ((int)threadIdx.x >= off) sh[threadIdx.x] += t;
        __syncthreads();
    }
    g_partials_scan[threadIdx.x] = sh[threadIdx.x] - v;
}

__global__ void k_scan3(int n) {
    int i = blockIdx.x * blockDim.x + threadIdx.x;
    if (i < n) {
        int cnt  = g_cnt[i];
        int incl = g_rowstart[i] + g_partials_scan[i / SCAN_B];
        g_rowstart[i] = incl - cnt;
        if (i == n - 1) g_rowstart[n] = incl;
        g_dinv[i] = rsqrtf((float)cnt + 1.0f);
    }
}

__global__ void k_bucket(const void* __restrict__ ei, int e, int n) {
    int i = blockIdx.x * blockDim.x + threadIdx.x;
    if (i < e) {
        int s = edge_at(ei, i);
        int d = edge_at(ei, (size_t)e + i);
        if ((unsigned)d < (unsigned)n && (unsigned)s < (unsigned)n) {
            int pos = atomicAdd(&g_cursor[d], 1);
            g_src_sorted[g_rowstart[d] + pos] = s;
        }
    }
}

// ---------------- W pre-split: fp32 [k][n] -> bf16 hi/lo [n][k] ----------------
__global__ __launch_bounds__(256) void k_splitW(const float* __restrict__ W) {
    int idx = blockIdx.x * blockDim.x + threadIdx.x;   // 0..16383
    int k = idx >> 7, nn = idx & 127;
    float v = W[idx];                                   // W[k][nn], coalesced
    __nv_bfloat16 h = __float2bfloat16_rn(v);
    __nv_bfloat16 l = __float2bfloat16_rn(v - __bfloat162float(h));
    g_Wh[nn * HID + k] = h;
    g_Wl[nn * HID + k] = l;
}

// ---------------- Tensor-core GEMM: [n,128] @ [128,128] -> g_bufB ----------------
// bf16 split (hi/lo), 3 mma products ~= fp32 accuracy. mma.m16n8k16.
// Block: 64 rows x 128 cols, 256 threads = 8 warps (4 m x 2 n), warp tile 16x64.
// W comes PRE-SPLIT from g_Wh/g_Wl (n-major) -> smem load is a pure vector copy.
// mode==0: A = Aext.  mode==1: A = relu(g_bufC * g_scale + g_shift).
#define GMB 64
#define GKB 32
#define GSTR 40   // bf16 stride: 80B = 20 words -> conflict-free fragment loads

__device__ __forceinline__ void mma_bf16(
    float& c0, float& c1, float& c2, float& c3,
    unsigned a0, unsigned a1, unsigned a2, unsigned a3,
    unsigned b0, unsigned b1)
{
    asm volatile(
        "mma.sync.aligned.m16n8k16.row.col.f32.bf16.bf16.f32 "
        "{%0,%1,%2,%3}, {%4,%5,%6,%7}, {%8,%9}, {%0,%1,%2,%3};"
        : "+f"(c0), "+f"(c1), "+f"(c2), "+f"(c3)
        : "r"(a0), "r"(a1), "r"(a2), "r"(a3), "r"(b0), "r"(b1));
}

__device__ __forceinline__ __nv_bfloat162 split2(float a, float b, __nv_bfloat162& lo) {
    __nv_bfloat16 ha = __float2bfloat16_rn(a);
    __nv_bfloat16 hb = __float2bfloat16_rn(b);
    __nv_bfloat16 la = __float2bfloat16_rn(a - __bfloat162float(ha));
    __nv_bfloat16 lb = __float2bfloat16_rn(b - __bfloat162float(hb));
    lo = __halves2bfloat162(la, lb);
    return __halves2bfloat162(ha, hb);
}

__global__ __launch_bounds__(256) void k_gemm_tc(
    const float* __restrict__ Aext, int mode, int n)
{
    __shared__ __align__(16) __nv_bfloat16 Ah[GMB][GSTR];
    __shared__ __align__(16) __nv_bfloat16 Al[GMB][GSTR];
    __shared__ __align__(16) __nv_bfloat16 Wh[HID][GSTR];  // [n][k-chunk]
    __shared__ __align__(16) __nv_bfloat16 Wl[HID][GSTR];

    int tid  = threadIdx.x;
    int warp = tid >> 5;
    int lane = tid & 31;
    int group = lane >> 2;      // 0..7
    int tig   = lane & 3;       // 0..3
    int wm = (warp >> 1) * 16;  // warp row offset 0/16/32/48
    int wn = (warp & 1) * 64;   // warp col offset 0/64
    int br = blockIdx.x * GMB;
    const float* A = mode ? (const float*)g_bufC : Aext;

    float acc[8][4];
#pragma unroll
    for (int j = 0; j < 8; j++)
#pragma unroll
        for (int q = 0; q < 4; q++) acc[j][q] = 0.f;

    for (int kb = 0; kb < HID; kb += GKB) {
        // ---- load + split A chunk: 64 rows x 32 k (packed 32-bit smem stores) ----
#pragma unroll
        for (int u = 0; u < 2; u++) {
            int idx = tid + u * 256;        // 0..511 float4 slots
            int row = idx >> 3;             // 0..63
            int c4  = idx & 7;              // 0..7 (float4 within 32-k slab)
            int gr  = br + row;
            float4 v = make_float4(0.f, 0.f, 0.f, 0.f);
            if (gr < n) v = ((const float4*)A)[(size_t)gr * 32 + (kb >> 2) + c4];
            if (mode) {
                float4 sc = ((const float4*)g_scale)[(kb >> 2) + c4];
                float4 sh = ((const float4*)g_shift)[(kb >> 2) + c4];
                v.x = fmaxf(fmaf(v.x, sc.x, sh.x), 0.f);
                v.y = fmaxf(fmaf(v.y, sc.y, sh.y), 0.f);
                v.z = fmaxf(fmaf(v.z, sc.z, sh.z), 0.f);
                v.w = fmaxf(fmaf(v.w, sc.w, sh.w), 0.f);
            }
            int kc = c4 * 4;
            __nv_bfloat162 lo0, lo1;
            __nv_bfloat162 hi0 = split2(v.x, v.y, lo0);
            __nv_bfloat162 hi1 = split2(v.z, v.w, lo1);
            *(__nv_bfloat162*)&Ah[row][kc]     = hi0;
            *(__nv_bfloat162*)&Ah[row][kc + 2] = hi1;
            *(__nv_bfloat162*)&Al[row][kc]     = lo0;
            *(__nv_bfloat162*)&Al[row][kc + 2] = lo1;
        }
        // ---- copy pre-split W chunk: 128 n-rows x 32 k, pure int4 copies ----
#pragma unroll
        for (int u = 0; u < 2; u++) {
            int idx = tid + u * 256;        // 0..511 -> 128 rows x 4 int4
            int nr = idx >> 2;              // 0..127
            int q  = idx & 3;               // 0..3 (int4 = 8 bf16)
            *(int4*)&Wh[nr][q * 8] = *(const int4*)&g_Wh[nr * HID + kb + q * 8];
            *(int4*)&Wl[nr][q * 8] = *(const int4*)&g_Wl[nr * HID + kb + q * 8];
        }
        __syncthreads();

#pragma unroll
        for (int ks = 0; ks < 2; ks++) {
            int k0 = ks * 16;
            int ar0 = wm + group, ar1 = wm + group + 8;
            int ac0 = k0 + tig * 2, ac1 = k0 + tig * 2 + 8;
            unsigned ah0 = *(const unsigned*)&Ah[ar0][ac0];
            unsigned ah1 = *(const unsigned*)&Ah[ar1][ac0];
            unsigned ah2 = *(const unsigned*)&Ah[ar0][ac1];
            unsigned ah3 = *(const unsigned*)&Ah[ar1][ac1];
            unsigned al0 = *(const unsigned*)&Al[ar0][ac0];
            unsigned al1 = *(const unsigned*)&Al[ar1][ac0];
            unsigned al2 = *(const unsigned*)&Al[ar0][ac1];
            unsigned al3 = *(const unsigned*)&Al[ar1][ac1];
#pragma unroll
            for (int j = 0; j < 8; j++) {
                int nr = wn + j * 8 + group;
                unsigned bh0 = *(const unsigned*)&Wh[nr][ac0];
                unsigned bh1 = *(const unsigned*)&Wh[nr][ac1];
                unsigned bl0 = *(const unsigned*)&Wl[nr][ac0];
                unsigned bl1 = *(const unsigned*)&Wl[nr][ac1];
                mma_bf16(acc[j][0], acc[j][1], acc[j][2], acc[j][3],
                         ah0, ah1, ah2, ah3, bh0, bh1);
                mma_bf16(acc[j][0], acc[j][1], acc[j][2], acc[j][3],
                         ah0, ah1, ah2, ah3, bl0, bl1);
                mma_bf16(acc[j][0], acc[j][1], acc[j][2], acc[j][3],
                         al0, al1, al2, al3, bh0, bh1);
            }
        }
        __syncthreads();
    }
    // ---- store C fragments ----
    int row0 = br + wm + group;
    int row1 = row0 + 8;
#pragma unroll
    for (int j = 0; j < 8; j++) {
        int col = wn + j * 8 + tig * 2;
        if (row0 < n) *(float2*)&g_bufB[(size_t)row0 * HID + col]
            = make_float2(acc[j][0], acc[j][1]);
        if (row1 < n) *(float2*)&g_bufB[(size_t)row1 * HID + col]
            = make_float2(acc[j][2], acc[j][3]);
    }
}

// ---------------- small GEMM: relu(bn(g_bufC)) @ W2[128,10] -> g_bufB[n,10] ----------------
__global__ __launch_bounds__(256) void k_gemm10(
    const float* __restrict__ W, int n)
{
    __shared__ float Ws[HID * NOUT];
    int tid = threadIdx.x;
    for (int i = tid; i < HID * NOUT; i += blockDim.x) Ws[i] = W[i];
    __syncthreads();
    int warp = tid >> 5, lane = tid & 31;
    int row = blockIdx.x * (blockDim.x >> 5) + warp;
    if (row >= n) return;
    const float* A = (const float*)g_bufC;
    float a0 = fmaxf(fmaf(A[(size_t)row * HID + lane],      g_scale[lane],      g_shift[lane]),      0.f);
    float a1 = fmaxf(fmaf(A[(size_t)row * HID + 32 + lane], g_scale[lane + 32], g_shift[lane + 32]), 0.f);
    float a2 = fmaxf(fmaf(A[(size_t)row * HID + 64 + lane], g_scale[lane + 64], g_shift[lane + 64]), 0.f);
    float a3 = fmaxf(fmaf(A[(size_t)row * HID + 96 + lane], g_scale[lane + 96], g_shift[lane + 96]), 0.f);
#pragma unroll
    for (int c = 0; c < NOUT; c++) {
        float p = a0 * Ws[lane * NOUT + c]
                + a1 * Ws[(lane + 32) * NOUT + c]
                + a2 * Ws[(lane + 64) * NOUT + c]
                + a3 * Ws[(lane + 96) * NOUT + c];
#pragma unroll
        for (int off = 16; off > 0; off >>= 1)
            p += __shfl_down_sync(0xffffffffu, p, off);
        if (lane == 0) g_bufB[(size_t)row * NOUT + c] = p;
    }
}

// ---------------- aggregation + fused BN stats, width 128 ----------------
__global__ __launch_bounds__(256) void k_agg128(
    const float* __restrict__ bias, int n, int layer)
{
    __shared__ float shs[8][HID];
    __shared__ float shq[8][HID];
    int ty = threadIdx.y;
    int lane = threadIdx.x;
    int node = blockIdx.x * 8 + ty;
    bool active = node < n;
    const float4* hp = (const float4*)g_bufB;

    float4 o = make_float4(0.f, 0.f, 0.f, 0.f);
    if (active) {
        float di = g_dinv[node];
        float4 v = hp[(size_t)node * 32 + lane];
        float4 acc;
        acc.x = di * v.x; acc.y = di * v.y; acc.z = di * v.z; acc.w = di * v.w;
        int beg = g_rowstart[node], end = g_rowstart[node + 1];
        int j = beg;
        for (; j + 1 < end; j += 2) {
            int s0 = g_src_sorted[j];
            int s1 = g_src_sorted[j + 1];
            float w0 = g_dinv[s0];
            float w1 = g_dinv[s1];
            float4 m0 = hp[(size_t)s0 * 32 + lane];
            float4 m1 = hp[(size_t)s1 * 32 + lane];
            acc.x += w0 * m0.x + w1 * m1.x;
            acc.y += w0 * m0.y + w1 * m1.y;
            acc.z += w0 * m0.z + w1 * m1.z;
            acc.w += w0 * m0.w + w1 * m1.w;
        }
        if (j < end) {
            int s = g_src_sorted[j];
            float w = g_dinv[s];
            float4 m = hp[(size_t)s * 32 + lane];
            acc.x += w * m.x; acc.y += w * m.y; acc.z += w * m.z; acc.w += w * m.w;
        }
        float4 bb = ((const float4*)bias)[lane];
        o.x = fmaf(di, acc.x, bb.x); o.y = fmaf(di, acc.y, bb.y);
        o.z = fmaf(di, acc.z, bb.z); o.w = fmaf(di, acc.w, bb.w);
        ((float4*)g_bufC)[(size_t)node * 32 + lane] = o;
    }

    *(float4*)&shs[ty][lane * 4] = o;
    *(float4*)&shq[ty][lane * 4] = make_float4(o.x * o.x, o.y * o.y, o.z * o.z, o.w * o.w);
    __syncthreads();
    int tid = ty * 32 + lane;
    if (tid < HID) {
        float s = 0.f, q = 0.f;
#pragma unroll
        for (int r = 0; r < 8; r++) { s += shs[r][tid]; q += shq[r][tid]; }
        atomicAdd(&g_cs[layer][tid], s);
        atomicAdd(&g_cq[layer][tid], q);
    }
}

// width-10 variant (final layer): reads g_bufB[n,10], writes d_out
__global__ __launch_bounds__(256) void k_agg10(
    const float* __restrict__ bias, float* __restrict__ out, int n)
{
    int node = blockIdx.x * blockDim.y + threadIdx.y;
    if (node >= n) return;
    int lane = threadIdx.x;
    const float* h = (const float*)g_bufB;
    float di = g_dinv[node];
    float acc = 0.0f;
    if (lane < NOUT) acc = di * h[(size_t)node * NOUT + lane];
    int beg = g_rowstart[node], end = g_rowstart[node + 1];
    for (int j = beg; j < end; j++) {
        int s = g_src_sorted[j];
        if ((unsigned)s >= (unsigned)n) continue;
        float w = g_dinv[s];
        if (lane < NOUT) acc += w * h[(size_t)s * NOUT + lane];
    }
    if (lane < NOUT) out[(size_t)node * NOUT + lane] = di * acc + bias[lane];
}

// ---------------- BN finalize ----------------
__global__ __launch_bounds__(128) void k_bnfinal(
    const float* __restrict__ g, const float* __restrict__ be,
    int layer, int n)
{
    int c = threadIdx.x;
    float inv_n = 1.0f / (float)n;
    float mu  = g_cs[layer][c] * inv_n;
    float var = fmaxf(g_cq[layer][c] * inv_n - mu * mu, 0.0f);
    float sc = g[c] * rsqrtf(var + BN_EPS);
    g_scale[c] = sc;
    g_shift[c] = fmaf(-mu, sc, be[c]);
}

// ---------------- host launcher: kernel launches ONLY ----------------
extern "C" void kernel_launch(void* const* d_in, const int* in_sizes, int n_in,
                              void* d_out, int out_size)
{
    const float* x  = (const float*)d_in[0];
    const void*  ei = d_in[1];
    const float* W0 = (const float*)d_in[2];  const float* b0 = (const float*)d_in[3];
    const float* g0 = (const float*)d_in[4];  const float* be0 = (const float*)d_in[5];
    const float* W1 = (const float*)d_in[6];  const float* b1 = (const float*)d_in[7];
    const float* g1 = (const float*)d_in[8];  const float* be1 = (const float*)d_in[9];
    const float* W2 = (const float*)d_in[10]; const float* b2 = (const float*)d_in[11];

    int n = in_sizes[0] / HID;
    int e = in_sizes[1] / 2;
    float* out = (float*)d_out;

    int nb_n256 = (n + 255) / 256;
    int nb_e256 = (e + 255) / 256;
    int nb_scan = (n + SCAN_B - 1) / SCAN_B;

    // ---- dtype probe + CSR build ----
    k_detect<<<1, 256>>>((const unsigned int*)ei);
    k_zero<<<nb_n256, 256>>>(n);
    k_count<<<nb_e256, 256>>>(ei, e, n);
    k_scan1<<<nb_scan, SCAN_B>>>(n);
    k_scan2<<<1, 256>>>(nb_scan);
    k_scan3<<<nb_n256, 256>>>(n);
    k_bucket<<<nb_e256, 256>>>(ei, e, n);

    dim3 aggBlk(32, 8);
    int aggGrid = (n + 7) / 8;
    int gemmGrid = (n + GMB - 1) / GMB;

    // ---- layer 0 ----
    k_splitW<<<64, 256>>>(W0);
    k_gemm_tc<<<gemmGrid, 256>>>(x, 0, n);
    k_agg128<<<aggGrid, aggBlk>>>(b0, n, 0);
    k_bnfinal<<<1, 128>>>(g0, be0, 0, n);

    // ---- layer 1 (BN0 apply fused into A-load) ----
    k_splitW<<<64, 256>>>(W1);
    k_gemm_tc<<<gemmGrid, 256>>>(x, 1, n);
    k_agg128<<<aggGrid, aggBlk>>>(b1, n, 1);
    k_bnfinal<<<1, 128>>>(g1, be1, 1, n);

    // ---- layer 2 (BN1 apply fused into A-load; output) ----
    k_gemm10<<<(n + 7) / 8, 256>>>(W2, n);
    k_agg10<<<aggGrid, aggBlk>>>(b2, out, n);
}

// round 8
// speedup vs baseline: 1.4743x; 1.0534x over previous
#include <cuda_runtime.h>
#include <cuda_bf16.h>
#include <math.h>

// ---------------- problem constants (match dataset) ----------------
#define NMAXN 100000
#define EMAXE 1600000
#define HID 128
#define NOUT 10
#define BN_EPS 1e-5f

// ---------------- static device scratch (alloc-free rule) ----------------
__device__ __align__(256) float g_bufB[(size_t)NMAXN * HID]; // gemm output (pre-scaled msg)
__device__ __align__(256) float g_bufC[(size_t)NMAXN * HID]; // aggregation output
__device__ __align__(256) int   g_cnt[NMAXN];
__device__ __align__(256) int   g_rowstart[NMAXN + 1];
__device__ __align__(256) int   g_cursor[NMAXN];
__device__ __align__(256) int   g_src_sorted[EMAXE];
__device__ __align__(256) float g_dinv[NMAXN];
__device__ __align__(256) float g_cs[2][HID];   // per-layer column sums
__device__ __align__(256) float g_cq[2][HID];   // per-layer column sumsq
__device__ __align__(256) float g_scale[HID];
__device__ __align__(256) float g_shift[HID];
__device__ __align__(256) int   g_partials[256];
__device__ __align__(256) int   g_partials_scan[256];
// pre-split W (hi/lo bf16), transposed to [n][k] (n-major), both 128-wide layers
__device__ __align__(256) __nv_bfloat16 g_Wh[2][HID * HID];
__device__ __align__(256) __nv_bfloat16 g_Wl[2][HID * HID];
__device__ int g_is64;   // 1 if edge_index is int64, 0 if int32

__device__ __forceinline__ int edge_at(const void* ei, size_t idx) {
    if (g_is64) return (int)((const long long*)ei)[idx];
    return ((const int*)ei)[idx];
}

// ---------------- zero + fused dtype detection ----------------
// int64 nonneg small indices (little-endian): every odd 32-bit word is 0.
__global__ void k_zero(const unsigned int* __restrict__ raw, int n) {
    int i = blockIdx.x * blockDim.x + threadIdx.x;
    if (i < n) { g_cnt[i] = 0; g_cursor[i] = 0; }
    if (i < HID) {
        g_cs[0][i] = 0.f; g_cq[0][i] = 0.f;
        g_cs[1][i] = 0.f; g_cq[1][i] = 0.f;
    }
    if (blockIdx.x == 0) {
        __shared__ int any;
        if (threadIdx.x == 0) any = 0;
        __syncthreads();
        unsigned int w = raw[threadIdx.x * 2 + 1];   // first 512 words
        if (w != 0u) atomicOr(&any, 1);
        __syncthreads();
        if (threadIdx.x == 0) g_is64 = any ? 0 : 1;
    }
}

__global__ void k_count(const void* __restrict__ ei, int e, int n) {
    int i = blockIdx.x * blockDim.x + threadIdx.x;
    if (i < e) {
        int d = edge_at(ei, (size_t)e + i);
        if ((unsigned)d < (unsigned)n) atomicAdd(&g_cnt[d], 1);
    }
}

#define SCAN_B 1024
__global__ void k_scan1(int n) {
    __shared__ int sh[SCAN_B];
    int i = blockIdx.x * SCAN_B + threadIdx.x;
    int v = (i < n) ? g_cnt[i] : 0;
    sh[threadIdx.x] = v;
    __syncthreads();
    for (int off = 1; off < SCAN_B; off <<= 1) {
        int t = 0;
        if ((int)threadIdx.x >= off) t = sh[threadIdx.x - off];
        __syncthreads();
        if ((int)threadIdx.x >= off) sh[threadIdx.x] += t;
        __syncthreads();
    }
    if (i < n) g_rowstart[i] = sh[threadIdx.x];
    if (threadIdx.x == SCAN_B - 1) g_partials[blockIdx.x] = sh[SCAN_B - 1];
}

__global__ void k_scan2(int nb) {
    __shared__ int sh[256];
    int v = ((int)threadIdx.x < nb) ? g_partials[threadIdx.x] : 0;
    sh[threadIdx.x] = v;
    __syncthreads();
    for (int off = 1; off < 256; off <<= 1) {
        int t = 0;
        if ((int)threadIdx.x >= off) t = sh[threadIdx.x - off];
        __syncthreads();
        if ((int)threadIdx.x >= off) sh[threadIdx.x] += t;
        __syncthreads();
    }
    g_partials_scan[threadIdx.x] = sh[threadIdx.x] - v;
}

__global__ void k_scan3(int n) {
    int i = blockIdx.x * blockDim.x + threadIdx.x;
    if (i < n) {
        int cnt  = g_cnt[i];
        int incl = g_rowstart[i] + g_partials_scan[i / SCAN_B];
        g_rowstart[i] = incl - cnt;
        if (i == n - 1) g_rowstart[n] = incl;
        g_dinv[i] = rsqrtf((float)cnt + 1.0f);
    }
}

__global__ void k_bucket(const void* __restrict__ ei, int e, int n) {
    int i = blockIdx.x * blockDim.x + threadIdx.x;
    if (i < e) {
        int s = edge_at(ei, i);
        int d = edge_at(ei, (size_t)e + i);
        if ((unsigned)d < (unsigned)n && (unsigned)s < (unsigned)n) {
            int pos = atomicAdd(&g_cursor[d], 1);
            g_src_sorted[g_rowstart[d] + pos] = s;
        }
    }
}

// ---------------- W pre-split (both layers): fp32 [k][n] -> bf16 hi/lo [n][k] ----------------
__global__ __launch_bounds__(256) void k_splitW2(
    const float* __restrict__ W0, const float* __restrict__ W1)
{
    int idx = blockIdx.x * blockDim.x + threadIdx.x;   // 0..32767
    int layer = idx >> 14;
    int r = idx & 16383;
    int k = r >> 7, nn = r & 127;
    float v = (layer ? W1 : W0)[r];
    __nv_bfloat16 h = __float2bfloat16_rn(v);
    __nv_bfloat16 l = __float2bfloat16_rn(v - __bfloat162float(h));
    g_Wh[layer][nn * HID + k] = h;
    g_Wl[layer][nn * HID + k] = l;
}

// ---------------- Tensor-core GEMM: msg = dinv * ([n,128] @ [128,128]) -> g_bufB ----------------
// bf16 split (hi/lo), 3 mma products ~= fp32 accuracy. mma.m16n8k16.
// Block: 128 rows x 128 cols, 256 threads = 8 warps (4m x 2n), warp tile 32x64.
// mode==0: A = Aext.  mode==1: A = relu(g_bufC * g_scale + g_shift).
#define GMB 128
#define GKB 32
#define GSTR 40   // bf16 stride: 80B = 20 words -> conflict-free fragment loads

__device__ __forceinline__ void mma_bf16(
    float& c0, float& c1, float& c2, float& c3,
    unsigned a0, unsigned a1, unsigned a2, unsigned a3,
    unsigned b0, unsigned b1)
{
    asm volatile(
        "mma.sync.aligned.m16n8k16.row.col.f32.bf16.bf16.f32 "
        "{%0,%1,%2,%3}, {%4,%5,%6,%7}, {%8,%9}, {%0,%1,%2,%3};"
        : "+f"(c0), "+f"(c1), "+f"(c2), "+f"(c3)
        : "r"(a0), "r"(a1), "r"(a2), "r"(a3), "r"(b0), "r"(b1));
}

__device__ __forceinline__ __nv_bfloat162 split2(float a, float b, __nv_bfloat162& lo) {
    __nv_bfloat16 ha = __float2bfloat16_rn(a);
    __nv_bfloat16 hb = __float2bfloat16_rn(b);
    __nv_bfloat16 la = __float2bfloat16_rn(a - __bfloat162float(ha));
    __nv_bfloat16 lb = __float2bfloat16_rn(b - __bfloat162float(hb));
    lo = __halves2bfloat162(la, lb);
    return __halves2bfloat162(ha, hb);
}

__global__ __launch_bounds__(256) void k_gemm_tc(
    const float* __restrict__ Aext, int mode, int layer, int n)
{
    __shared__ __align__(16) __nv_bfloat16 Ah[GMB][GSTR];
    __shared__ __align__(16) __nv_bfloat16 Al[GMB][GSTR];
    __shared__ __align__(16) __nv_bfloat16 Wh[HID][GSTR];  // [n][k-chunk]
    __shared__ __align__(16) __nv_bfloat16 Wl[HID][GSTR];

    int tid  = threadIdx.x;
    int warp = tid >> 5;
    int lane = tid & 31;
    int group = lane >> 2;      // 0..7
    int tig   = lane & 3;       // 0..3
    int wm = (warp >> 1) * 32;  // warp row offset 0/32/64/96
    int wn = (warp & 1) * 64;   // warp col offset 0/64
    int br = blockIdx.x * GMB;
    const float* A = mode ? (const float*)g_bufC : Aext;
    const __nv_bfloat16* GWh = g_Wh[layer];
    const __nv_bfloat16* GWl = g_Wl[layer];

    float acc[2][8][4];
#pragma unroll
    for (int mi = 0; mi < 2; mi++)
#pragma unroll
        for (int j = 0; j < 8; j++)
#pragma unroll
            for (int q = 0; q < 4; q++) acc[mi][j][q] = 0.f;

    for (int kb = 0; kb < HID; kb += GKB) {
        // ---- load + split A chunk: 128 rows x 32 k ----
#pragma unroll
        for (int u = 0; u < 4; u++) {
            int idx = tid + u * 256;        // 0..1023 float4 slots
            int row = idx >> 3;             // 0..127
            int c4  = idx & 7;              // 0..7
            int gr  = br + row;
            float4 v = make_float4(0.f, 0.f, 0.f, 0.f);
            if (gr < n) v = ((const float4*)A)[(size_t)gr * 32 + (kb >> 2) + c4];
            if (mode) {
                float4 sc = ((const float4*)g_scale)[(kb >> 2) + c4];
                float4 sh = ((const float4*)g_shift)[(kb >> 2) + c4];
                v.x = fmaxf(fmaf(v.x, sc.x, sh.x), 0.f);
                v.y = fmaxf(fmaf(v.y, sc.y, sh.y), 0.f);
                v.z = fmaxf(fmaf(v.z, sc.z, sh.z), 0.f);
                v.w = fmaxf(fmaf(v.w, sc.w, sh.w), 0.f);
            }
            int kc = c4 * 4;
            __nv_bfloat162 lo0, lo1;
            __nv_bfloat162 hi0 = split2(v.x, v.y, lo0);
            __nv_bfloat162 hi1 = split2(v.z, v.w, lo1);
            *(__nv_bfloat162*)&Ah[row][kc]     = hi0;
            *(__nv_bfloat162*)&Ah[row][kc + 2] = hi1;
            *(__nv_bfloat162*)&Al[row][kc]     = lo0;
            *(__nv_bfloat162*)&Al[row][kc + 2] = lo1;
        }
        // ---- copy pre-split W chunk: 128 n-rows x 32 k, pure int4 copies ----
#pragma unroll
        for (int u = 0; u < 2; u++) {
            int idx = tid + u * 256;        // 0..511 -> 128 rows x 4 int4
            int nr = idx >> 2;              // 0..127
            int q  = idx & 3;               // 0..3
            *(int4*)&Wh[nr][q * 8] = *(const int4*)&GWh[nr * HID + kb + q * 8];
            *(int4*)&Wl[nr][q * 8] = *(const int4*)&GWl[nr * HID + kb + q * 8];
        }
        __syncthreads();

#pragma unroll
        for (int ks = 0; ks < 2; ks++) {
            int k0 = ks * 16;
            int ac0 = k0 + tig * 2, ac1 = k0 + tig * 2 + 8;
            unsigned ah[2][4], al[2][4];
#pragma unroll
            for (int mi = 0; mi < 2; mi++) {
                int ar0 = wm + mi * 16 + group, ar1 = ar0 + 8;
                ah[mi][0] = *(const unsigned*)&Ah[ar0][ac0];
                ah[mi][1] = *(const unsigned*)&Ah[ar1][ac0];
                ah[mi][2] = *(const unsigned*)&Ah[ar0][ac1];
                ah[mi][3] = *(const unsigned*)&Ah[ar1][ac1];
                al[mi][0] = *(const unsigned*)&Al[ar0][ac0];
                al[mi][1] = *(const unsigned*)&Al[ar1][ac0];
                al[mi][2] = *(const unsigned*)&Al[ar0][ac1];
                al[mi][3] = *(const unsigned*)&Al[ar1][ac1];
            }
#pragma unroll
            for (int j = 0; j < 8; j++) {
                int nr = wn + j * 8 + group;
                unsigned bh0 = *(const unsigned*)&Wh[nr][ac0];
                unsigned bh1 = *(const unsigned*)&Wh[nr][ac1];
                unsigned bl0 = *(const unsigned*)&Wl[nr][ac0];
                unsigned bl1 = *(const unsigned*)&Wl[nr][ac1];
#pragma unroll
                for (int mi = 0; mi < 2; mi++) {
                    mma_bf16(acc[mi][j][0], acc[mi][j][1], acc[mi][j][2], acc[mi][j][3],
                             ah[mi][0], ah[mi][1], ah[mi][2], ah[mi][3], bh0, bh1);
                    mma_bf16(acc[mi][j][0], acc[mi][j][1], acc[mi][j][2], acc[mi][j][3],
                             ah[mi][0], ah[mi][1], ah[mi][2], ah[mi][3], bl0, bl1);
                    mma_bf16(acc[mi][j][0], acc[mi][j][1], acc[mi][j][2], acc[mi][j][3],
                             al[mi][0], al[mi][1], al[mi][2], al[mi][3], bh0, bh1);
                }
            }
        }
        __syncthreads();
    }
    // ---- store msg = dinv[row] * C ----
#pragma unroll
    for (int mi = 0; mi < 2; mi++) {
        int row0 = br + wm + mi * 16 + group;
        int row1 = row0 + 8;
        float d0 = (row0 < n) ? g_dinv[row0] : 0.f;
        float d1 = (row1 < n) ? g_dinv[row1] : 0.f;
#pragma unroll
        for (int j = 0; j < 8; j++) {
            int col = wn + j * 8 + tig * 2;
            if (row0 < n) *(float2*)&g_bufB[(size_t)row0 * HID + col]
                = make_float2(d0 * acc[mi][j][0], d0 * acc[mi][j][1]);
            if (row1 < n) *(float2*)&g_bufB[(size_t)row1 * HID + col]
                = make_float2(d1 * acc[mi][j][2], d1 * acc[mi][j][3]);
        }
    }
}

// ---------------- small GEMM: msg10 = dinv * (relu(bn(g_bufC)) @ W2) -> g_bufB[n,10] ----------------
__global__ __launch_bounds__(256) void k_gemm10(
    const float* __restrict__ W, int n)
{
    __shared__ float Ws[HID * NOUT];
    int tid = threadIdx.x;
    for (int i = tid; i < HID * NOUT; i += blockDim.x) Ws[i] = W[i];
    __syncthreads();
    int warp = tid >> 5, lane = tid & 31;
    int row = blockIdx.x * (blockDim.x >> 5) + warp;
    if (row >= n) return;
    const float* A = (const float*)g_bufC;
    float a0 = fmaxf(fmaf(A[(size_t)row * HID + lane],      g_scale[lane],      g_shift[lane]),      0.f);
    float a1 = fmaxf(fmaf(A[(size_t)row * HID + 32 + lane], g_scale[lane + 32], g_shift[lane + 32]), 0.f);
    float a2 = fmaxf(fmaf(A[(size_t)row * HID + 64 + lane], g_scale[lane + 64], g_shift[lane + 64]), 0.f);
    float a3 = fmaxf(fmaf(A[(size_t)row * HID + 96 + lane], g_scale[lane + 96], g_shift[lane + 96]), 0.f);
    float di = g_dinv[row];
#pragma unroll
    for (int c = 0; c < NOUT; c++) {
        float p = a0 * Ws[lane * NOUT + c]
                + a1 * Ws[(lane + 32) * NOUT + c]
                + a2 * Ws[(lane + 64) * NOUT + c]
                + a3 * Ws[(lane + 96) * NOUT + c];
#pragma unroll
        for (int off = 16; off > 0; off >>= 1)
            p += __shfl_down_sync(0xffffffffu, p, off);
        if (lane == 0) g_bufB[(size_t)row * NOUT + c] = di * p;
    }
}

// ---------------- aggregation + fused BN stats, width 128 ----------------
// msg is pre-scaled: out[i] = dinv[i] * (sum_{src} msg[src] + msg[i]) + bias
__global__ __launch_bounds__(256) void k_agg128(
    const float* __restrict__ bias, int n, int layer)
{
    __shared__ float shs[8][HID];
    __shared__ float shq[8][HID];
    int ty = threadIdx.y;
    int lane = threadIdx.x;
    int node = blockIdx.x * 8 + ty;
    bool active = node < n;
    const float4* hp = (const float4*)g_bufB;

    float4 o = make_float4(0.f, 0.f, 0.f, 0.f);
    if (active) {
        float di = g_dinv[node];
        float4 acc = hp[(size_t)node * 32 + lane];      // msg[node] (self-loop)
        int beg = g_rowstart[node], end = g_rowstart[node + 1];
        int j = beg;
        for (; j + 3 < end; j += 4) {
            int s0 = g_src_sorted[j];
            int s1 = g_src_sorted[j + 1];
            int s2 = g_src_sorted[j + 2];
            int s3 = g_src_sorted[j + 3];
            float4 m0 = hp[(size_t)s0 * 32 + lane];
            float4 m1 = hp[(size_t)s1 * 32 + lane];
            float4 m2 = hp[(size_t)s2 * 32 + lane];
            float4 m3 = hp[(size_t)s3 * 32 + lane];
            acc.x += (m0.x + m1.x) + (m2.x + m3.x);
            acc.y += (m0.y + m1.y) + (m2.y + m3.y);
            acc.z += (m0.z + m1.z) + (m2.z + m3.z);
            acc.w += (m0.w + m1.w) + (m2.w + m3.w);
        }
        for (; j < end; j++) {
            int s = g_src_sorted[j];
            float4 m = hp[(size_t)s * 32 + lane];
            acc.x += m.x; acc.y += m.y; acc.z += m.z; acc.w += m.w;
        }
        float4 bb = ((const float4*)bias)[lane];
        o.x = fmaf(di, acc.x, bb.x); o.y = fmaf(di, acc.y, bb.y);
        o.z = fmaf(di, acc.z, bb.z); o.w = fmaf(di, acc.w, bb.w);
        ((float4*)g_bufC)[(size_t)node * 32 + lane] = o;
    }

    *(float4*)&shs[ty][lane * 4] = o;
    *(float4*)&shq[ty][lane * 4] = make_float4(o.x * o.x, o.y * o.y, o.z * o.z, o.w * o.w);
    __syncthreads();
    int tid = ty * 32 + lane;
    if (tid < HID) {
        float s = 0.f, q = 0.f;
#pragma unroll
        for (int r = 0; r < 8; r++) { s += shs[r][tid]; q += shq[r][tid]; }
        atomicAdd(&g_cs[layer][tid], s);
        atomicAdd(&g_cq[layer][tid], q);
    }
}

// width-10 final agg: two edges per iteration (lane halves), writes d_out
__global__ __launch_bounds__(256) void k_agg10(
    const float* __restrict__ bias, float* __restrict__ out, int n)
{
    int ty = threadIdx.y;
    int lane = threadIdx.x;
    int node = blockIdx.x * 8 + ty;
    if (node >= n) return;
    int half = lane >> 4;       // 0/1
    int c = lane & 15;          // column, active c < NOUT
    const float* h = (const float*)g_bufB;
    float di = g_dinv[node];
    float acc = 0.f;
    if (half == 0 && c < NOUT) acc = h[(size_t)node * NOUT + c];  // self msg
    int beg = g_rowstart[node], end = g_rowstart[node + 1];
    for (int j = beg + half; j < end; j += 2) {
        int s = g_src_sorted[j];
        if (c < NOUT) acc += h[(size_t)s * NOUT + c];
    }
    acc += __shfl_xor_sync(0xffffffffu, acc, 16);
    if (half == 0 && c < NOUT)
        out[(size_t)node * NOUT + c] = fmaf(di, acc, bias[c]);
}

// ---------------- BN finalize ----------------
__global__ __launch_bounds__(128) void k_bnfinal(
    const float* __restrict__ g, const float* __restrict__ be,
    int layer, int n)
{
    int c = threadIdx.x;
    float inv_n = 1.0f / (float)n;
    float mu  = g_cs[layer][c] * inv_n;
    float var = fmaxf(g_cq[layer][c] * inv_n - mu * mu, 0.0f);
    float sc = g[c] * rsqrtf(var + BN_EPS);
    g_scale[c] = sc;
    g_shift[c] = fmaf(-mu, sc, be[c]);
}

// ---------------- host launcher: kernel launches ONLY ----------------
extern "C" void kernel_launch(void* const* d_in, const int* in_sizes, int n_in,
                              void* d_out, int out_size)
{
    const float* x  = (const float*)d_in[0];
    const void*  ei = d_in[1];
    const float* W0 = (const float*)d_in[2];  const float* b0 = (const float*)d_in[3];
    const float* g0 = (const float*)d_in[4];  const float* be0 = (const float*)d_in[5];
    const float* W1 = (const float*)d_in[6];  const float* b1 = (const float*)d_in[7];
    const float* g1 = (const float*)d_in[8];  const float* be1 = (const float*)d_in[9];
    const float* W2 = (const float*)d_in[10]; const float* b2 = (const float*)d_in[11];

    int n = in_sizes[0] / HID;
    int e = in_sizes[1] / 2;
    float* out = (float*)d_out;

    int nb_n256 = (n + 255) / 256;
    int nb_e256 = (e + 255) / 256;
    int nb_scan = (n + SCAN_B - 1) / SCAN_B;

    // ---- W pre-split (independent) + CSR build ----
    k_splitW2<<<128, 256>>>(W0, W1);
    k_zero<<<nb_n256, 256>>>((const unsigned int*)ei, n);
    k_count<<<nb_e256, 256>>>(ei, e, n);
    k_scan1<<<nb_scan, SCAN_B>>>(n);
    k_scan2<<<1, 256>>>(nb_scan);
    k_scan3<<<nb_n256, 256>>>(n);
    k_bucket<<<nb_e256, 256>>>(ei, e, n);

    dim3 aggBlk(32, 8);
    int aggGrid = (n + 7) / 8;
    int gemmGrid = (n + GMB - 1) / GMB;

    // ---- layer 0 ----
    k_gemm_tc<<<gemmGrid, 256>>>(x, 0, 0, n);
    k_agg128<<<aggGrid, aggBlk>>>(b0, n, 0);
    k_bnfinal<<<1, 128>>>(g0, be0, 0, n);

    // ---- layer 1 (BN0 apply fused into A-load) ----
    k_gemm_tc<<<gemmGrid, 256>>>(x, 1, 1, n);
    k_agg128<<<aggGrid, aggBlk>>>(b1, n, 1);
    k_bnfinal<<<1, 128>>>(g1, be1, 1, n);

    // ---- layer 2 (BN1 apply fused into A-load; output) ----
    k_gemm10<<<(n + 7) / 8, 256>>>(W2, n);
    k_agg10<<<aggGrid, aggBlk>>>(b2, out, n);
}